// round 9
// baseline (speedup 1.0000x reference)
#include <cuda_runtime.h>

// QuantumLayer: B=512, Q=14, L=2.
// Closed-form Heisenberg evaluation (see R1 derivation):
//   outs[b,i] = <s0| C^T R^T C^T Z_i C R C |s0>
// reduced to a 3-state linear DP over qubits. Shuffle-based, no smem, no
// barriers, 16 lanes per batch (2 batches per warp).
// Shape: 256 CTAs x 32 threads — confirmed optimum across the full sweep
// (32x256: 4.83us, 128x64: 4.51, 256x32: 4.32, 512x16: 4.38).
// This round: inactive-lane Sq defaults to 1.0 so the tail factor needs no
// select; x load issued first so the cold DRAM LDG overlaps w loads + MUFU.

#define QN 14
#define BN 512

__global__ void __launch_bounds__(32)
quantum_dp_kernel(const float* __restrict__ x,
                  const float* __restrict__ w,
                  float* __restrict__ out)
{
    const int tid = blockIdx.x * 32 + threadIdx.x;
    const int b = tid >> 4;        // 16 lanes per batch
    const int i = tid & 15;        // lane i owns qubit i (i>=14 inactive)

    // Lane-local table entries for qubit i of batch b.
    // Inactive lanes: Sq=1.0 so lane 13's tail (= Sq[14]) is identity.
    float Cq = 1.0f, Sq = 1.0f, Az = 1.0f, Ax = 0.0f;
    if (i < QN) {
        float xv = __ldg(&x[b * QN + i]);    // cold DRAM load — issue first
        float w0 = __ldg(&w[i]);
        float w1 = __ldg(&w[QN + i]);
        float s, c;
        __sincosf(xv + w0, &s, &c);          // angles compose on same axis
        Cq = c;            // <Z_i>
        Sq = s;            // <X_i>
        float s1, c1;
        __sincosf(w1, &s1, &c1);
        Az = c1;           // Z-choice coeff
        Ax = -s1;          // X-choice coeff
    }

    const unsigned m = 0xFFFFFFFFu;

    // Emit factors (qubit 0) — issued early, independent of the DP chain.
    float C0 = __shfl_sync(m, Cq, 0, 16);
    float S0 = __shfl_sync(m, Sq, 0, 16);

    // tail = Sq[i+1]; width-16 shfl_down clamps lane 15, lane 14 holds 1.0.
    float tail = __shfl_down_sync(m, Sq, 1, 16);

    // DP state: (p = Z-parity, x = last-was-X); (1,1) unreachable.
    float s00 = 0.0f;          // (0,0)
    float s10 = Az;            // (1,0)
    float s01 = Ax * tail;     // (0,1)

    // Descend t = i-1 .. 0. Shuffle sources are uniform per iteration
    // (broadcast) and independent of the DP chain -> fully pipelined.
    #pragma unroll
    for (int t = QN - 2; t >= 0; --t) {
        float cz = __shfl_sync(m, Az, t,     16);
        float cx = __shfl_sync(m, Ax, t,     16);
        float fC = __shfl_sync(m, Cq, t + 1, 16);
        float fS = __shfl_sync(m, Sq, t + 1, 16);
        if (t <= i - 1) {
            float n10 = cz * fmaf(fS, s01, s00);   // sigma=Z: p flips, x=0
            float n00 = cz * fC * s10;             // from (1,0)
            float n01 = cx * fmaf(fS, s00, s01);   // sigma=X: p keeps, x=1
            s00 = n00;
            s01 = n01;
            s10 = n10;
        }
    }

    // Final emit for qubit 0: (0,0)->1, (1,0)->Cq[0], (0,1)->Sq[0]
    if (i < QN)
        out[b * QN + i] = fmaf(C0, s10, fmaf(S0, s01, s00));
}

extern "C" void kernel_launch(void* const* d_in, const int* in_sizes, int n_in,
                              void* d_out, int out_size)
{
    const float* x = (const float*)d_in[0];   // [512, 14]
    const float* w = (const float*)d_in[1];   // [2, 14]
    float* out = (float*)d_out;               // [512, 14]

    // 512 batches * 16 lanes = 8192 threads = 256 CTAs x 32 (all resident)
    quantum_dp_kernel<<<(BN * 16) / 32, 32>>>(x, w, out);
}

// round 11
// speedup vs baseline: 1.3605x; 1.3605x over previous
#include <cuda_runtime.h>

// QuantumLayer: B=512, Q=14, L=2.
// Closed-form Heisenberg evaluation (see R1 derivation):
//   outs[b,i] = <s0| C^T R^T C^T Z_i C R C |s0>
// reduced to a 3-state linear DP over qubits. Shuffle-based, no smem, no
// barriers, 16 lanes per batch (2 batches per warp).
// 256 CTAs x 32 threads (single-warp CTAs, all resident) — the verbatim
// best-measured configuration (R4: 4.672us harness / 4.32us ncu). Later
// micro-variants measured inside the run-to-run noise band; reverted.

#define QN 14
#define BN 512

__global__ void __launch_bounds__(32)
quantum_dp_kernel(const float* __restrict__ x,
                  const float* __restrict__ w,
                  float* __restrict__ out)
{
    const int tid = blockIdx.x * 32 + threadIdx.x;
    const int b = tid >> 4;        // 16 lanes per batch
    const int i = tid & 15;        // lane i owns qubit i (i>=14 inactive)

    // Lane-local table entries for qubit i of batch b.
    float Cq = 1.0f, Sq = 0.0f, Az = 1.0f, Ax = 0.0f;
    if (i < QN) {
        float th = __ldg(&x[b * QN + i]) + __ldg(&w[i]);   // angles compose
        float s, c;
        __sincosf(th, &s, &c);      // fast MUFU path
        Cq = c;            // <Z_i>
        Sq = s;            // <X_i>
        float w1 = __ldg(&w[QN + i]);
        float s1, c1;
        __sincosf(w1, &s1, &c1);
        Az = c1;           // Z-choice coeff
        Ax = -s1;          // X-choice coeff
    }

    const unsigned m = 0xFFFFFFFFu;

    // Emit factors (qubit 0) — issued early, independent of the DP chain.
    float C0 = __shfl_sync(m, Cq, 0, 16);
    float S0 = __shfl_sync(m, Sq, 0, 16);

    // tail = Sq[i+1] (1.0 when i == Q-1); lane-varying source.
    float Sq_next = __shfl_down_sync(m, Sq, 1, 16);
    float tail = (i < QN - 1) ? Sq_next : 1.0f;

    // DP state: (p = Z-parity, x = last-was-X); (1,1) unreachable.
    float s00 = 0.0f;          // (0,0)
    float s10 = Az;            // (1,0)
    float s01 = Ax * tail;     // (0,1)

    // Descend t = i-1 .. 0. Shuffle sources are uniform per iteration
    // (broadcast) and independent of the DP chain -> fully pipelined.
    #pragma unroll
    for (int t = QN - 2; t >= 0; --t) {
        float cz = __shfl_sync(m, Az, t,     16);
        float cx = __shfl_sync(m, Ax, t,     16);
        float fC = __shfl_sync(m, Cq, t + 1, 16);
        float fS = __shfl_sync(m, Sq, t + 1, 16);
        if (t <= i - 1) {
            float n10 = cz * fmaf(fS, s01, s00);   // sigma=Z: p flips, x=0
            float n00 = cz * fC * s10;             // from (1,0)
            float n01 = cx * fmaf(fS, s00, s01);   // sigma=X: p keeps, x=1
            s00 = n00;
            s01 = n01;
            s10 = n10;
        }
    }

    // Final emit for qubit 0: (0,0)->1, (1,0)->Cq[0], (0,1)->Sq[0]
    if (i < QN)
        out[b * QN + i] = fmaf(C0, s10, fmaf(S0, s01, s00));
}

extern "C" void kernel_launch(void* const* d_in, const int* in_sizes, int n_in,
                              void* d_out, int out_size)
{
    const float* x = (const float*)d_in[0];   // [512, 14]
    const float* w = (const float*)d_in[1];   // [2, 14]
    float* out = (float*)d_out;               // [512, 14]

    // 512 batches * 16 lanes = 8192 threads = 256 CTAs x 32 (all resident)
    quantum_dp_kernel<<<(BN * 16) / 32, 32>>>(x, w, out);
}

// round 12
// speedup vs baseline: 1.3793x; 1.0138x over previous
#include <cuda_runtime.h>

// QuantumLayer: B=512, Q=14, L=2.  TERMINAL KERNEL.
//
// Closed-form Heisenberg evaluation (derivation in R1):
//   outs[b,i] = <s0| C^T R^T C^T Z_i C R C |s0>
// where s0 is the product state from composed angles theta_q = x[b,q]+w0[q],
// C is the adjacent CNOT chain, R = tensor RY(w1). Pauli propagation
// (Z_i -> Z_0..Z_i ; RY conjugation ; X_j -> X_j X_{j+1}) plus vanishing of
// all Y-collision terms on the real product state reduces the 2^(i+1)-term
// sum to a 3-state linear DP over qubits (state = (Z-parity, last-was-X);
// (1,1) unreachable).
//
// Implementation: shuffle-based, no smem, no barriers, 16 lanes per batch
// (2 batches per warp), 256 CTAs x 32 threads (single-warp CTAs, all
// resident in one wave). This shape won the full sweep
// (32x256: 4.83us, 128x64: 4.51, 256x32: 4.26-4.32, 512x16: 4.38).
// All pipes <1%, critical path ~900 cyc: remaining wall time is the fixed
// launch/distribution/ramp envelope; byte-identical binaries measured
// 4.26-4.61us (ncu), so further micro-changes are sub-noise.

#define QN 14
#define BN 512

__global__ void __launch_bounds__(32)
quantum_dp_kernel(const float* __restrict__ x,
                  const float* __restrict__ w,
                  float* __restrict__ out)
{
    const int tid = blockIdx.x * 32 + threadIdx.x;
    const int b = tid >> 4;        // 16 lanes per batch
    const int i = tid & 15;        // lane i owns qubit i (i>=14 inactive)

    // Lane-local table entries for qubit i of batch b.
    float Cq = 1.0f, Sq = 0.0f, Az = 1.0f, Ax = 0.0f;
    if (i < QN) {
        float th = __ldg(&x[b * QN + i]) + __ldg(&w[i]);   // angles compose
        float s, c;
        __sincosf(th, &s, &c);      // fast MUFU path (|th| small, err << 1e-3)
        Cq = c;            // <Z_i>
        Sq = s;            // <X_i>
        float w1 = __ldg(&w[QN + i]);
        float s1, c1;
        __sincosf(w1, &s1, &c1);
        Az = c1;           // Z-choice coeff
        Ax = -s1;          // X-choice coeff
    }

    const unsigned m = 0xFFFFFFFFu;

    // Emit factors (qubit 0) — issued early, independent of the DP chain.
    float C0 = __shfl_sync(m, Cq, 0, 16);
    float S0 = __shfl_sync(m, Sq, 0, 16);

    // tail = Sq[i+1] (1.0 when i == Q-1); lane-varying source.
    float Sq_next = __shfl_down_sync(m, Sq, 1, 16);
    float tail = (i < QN - 1) ? Sq_next : 1.0f;

    // DP state: (p = Z-parity, x = last-was-X); (1,1) unreachable.
    float s00 = 0.0f;          // (0,0)
    float s10 = Az;            // (1,0)
    float s01 = Ax * tail;     // (0,1)

    // Descend t = i-1 .. 0. Shuffle sources are uniform per iteration
    // (broadcast) and independent of the DP chain -> fully pipelined.
    #pragma unroll
    for (int t = QN - 2; t >= 0; --t) {
        float cz = __shfl_sync(m, Az, t,     16);
        float cx = __shfl_sync(m, Ax, t,     16);
        float fC = __shfl_sync(m, Cq, t + 1, 16);
        float fS = __shfl_sync(m, Sq, t + 1, 16);
        if (t <= i - 1) {
            float n10 = cz * fmaf(fS, s01, s00);   // sigma=Z: p flips, x=0
            float n00 = cz * fC * s10;             // from (1,0)
            float n01 = cx * fmaf(fS, s00, s01);   // sigma=X: p keeps, x=1
            s00 = n00;
            s01 = n01;
            s10 = n10;
        }
    }

    // Final emit for qubit 0: (0,0)->1, (1,0)->Cq[0], (0,1)->Sq[0]
    if (i < QN)
        out[b * QN + i] = fmaf(C0, s10, fmaf(S0, s01, s00));
}

extern "C" void kernel_launch(void* const* d_in, const int* in_sizes, int n_in,
                              void* d_out, int out_size)
{
    const float* x = (const float*)d_in[0];   // [512, 14]
    const float* w = (const float*)d_in[1];   // [2, 14]
    float* out = (float*)d_out;               // [512, 14]

    // 512 batches * 16 lanes = 8192 threads = 256 CTAs x 32 (all resident)
    quantum_dp_kernel<<<(BN * 16) / 32, 32>>>(x, w, out);
}